// round 8
// baseline (speedup 1.0000x reference)
#include <cuda_runtime.h>
#include <math.h>

#define N_NODES 8192
#define F_IN 128
#define F_OUT 64
#define NEG_SLOPE 0.2f
#define VERY_SMALL 1000000000000.0f
#define SD_BLOCKS 128
#define ROWS_PER_SD_BLOCK (N_NODES / SD_BLOCKS)   // 64 (8 per warp)

__device__ float g_s[N_NODES];
__device__ float g_d[N_NODES];
__device__ float g_bmax[SD_BLOCKS];   // per-block max of d

// Kernel A: fused prep + sd + per-block d-max.
// 128 blocks (one wave) x 256 thr, 64 rows/block, 8 rows/warp with
// front-batched h loads and interleaved shfl reduction chains.
__global__ __launch_bounds__(256) void sd_kernel(const float* __restrict__ h,
                                                 const float* __restrict__ w,
                                                 const float* __restrict__ a) {
    __shared__ float sw[F_IN * 65];   // padded: conflict-free row reads
    __shared__ float sa[F_IN];
    __shared__ float ws[F_IN];
    __shared__ float wd[F_IN];
    __shared__ float wmax[8];
    const int t = threadIdx.x;

    if (t < F_IN) sa[t] = a[t];
    const float4* w4 = reinterpret_cast<const float4*>(w);
    #pragma unroll
    for (int r = 0; r < 8; ++r) {
        int f = t + r * 256;
        float4 v = w4[f];
        int k = f >> 4;
        int j = (f & 15) * 4;
        float* dst = &sw[k * 65 + j];
        dst[0] = v.x; dst[1] = v.y; dst[2] = v.z; dst[3] = v.w;
    }
    __syncthreads();

    {   // threads 0-127: ws[k]; 128-255: wd[k]
        int k = t & 127;
        const float* arow = sa + ((t >= 128) ? F_OUT : 0);
        const float* wrow = &sw[k * 65];
        float acc = 0.f;
        #pragma unroll
        for (int j = 0; j < F_OUT; ++j)
            acc += wrow[j] * arow[j];
        if (t < 128) ws[k] = acc; else wd[k] = acc;
    }
    __syncthreads();

    const int warp = t >> 5;
    const int lane = t & 31;
    const int base = blockIdx.x * ROWS_PER_SD_BLOCK + warp * 8;
    const float4 wsv = reinterpret_cast<const float4*>(ws)[lane];
    const float4 wdv = reinterpret_cast<const float4*>(wd)[lane];
    const float4* h4 = reinterpret_cast<const float4*>(h);

    // Front-batch 8 independent row loads.
    float4 hv[8];
    #pragma unroll
    for (int r = 0; r < 8; ++r)
        hv[r] = h4[(size_t)(base + r) * (F_IN / 4) + lane];

    float s[8], d[8];
    #pragma unroll
    for (int r = 0; r < 8; ++r) {
        s[r] = hv[r].x * wsv.x + hv[r].y * wsv.y + hv[r].z * wsv.z + hv[r].w * wsv.w;
        d[r] = hv[r].x * wdv.x + hv[r].y * wdv.y + hv[r].z * wdv.z + hv[r].w * wdv.w;
    }
    // 16 interleaved shfl chains (8 rows x {s,d})
    #pragma unroll
    for (int o = 16; o > 0; o >>= 1) {
        #pragma unroll
        for (int r = 0; r < 8; ++r) {
            s[r] += __shfl_xor_sync(0xffffffffu, s[r], o);
            d[r] += __shfl_xor_sync(0xffffffffu, d[r], o);
        }
    }
    float dmax = -INFINITY;
    if (lane == 0) {
        #pragma unroll
        for (int r = 0; r < 8; ++r) {
            g_s[base + r] = s[r];
            g_d[base + r] = d[r];
            dmax = fmaxf(dmax, d[r]);
        }
        wmax[warp] = dmax;
    }
    __syncthreads();
    if (t == 0) {
        float m = wmax[0];
        #pragma unroll
        for (int k = 1; k < 8; ++k) m = fmaxf(m, wmax[k]);
        g_bmax[blockIdx.x] = m;
    }
}

__device__ __forceinline__ float block_reduce_sum(float v, float* red) {
    __syncthreads();   // safe reuse of red[] across successive reduces
    #pragma unroll
    for (int o = 16; o > 0; o >>= 1)
        v += __shfl_xor_sync(0xffffffffu, v, o);
    int warp = threadIdx.x >> 5;
    if ((threadIdx.x & 31) == 0) red[warp] = v;
    __syncthreads();
    if (warp == 0) {
        float x = (threadIdx.x < 8) ? red[threadIdx.x] : 0.f;
        #pragma unroll
        for (int o = 4; o > 0; o >>= 1)
            x += __shfl_xor_sync(0xffffffffu, x, o);
        if (threadIdx.x == 0) red[0] = x;
    }
    __syncthreads();
    return red[0];
}

// Kernel B: TWO rows per CTA (grid 4096), cross-row pipelined:
// row B's adj loads are issued BEFORE row A's reduce barrier so they are
// in flight during A's reduce + store (bar.sync does not drain LDGs).
// Stabilizer M_r = lrelu(s_r + max_j d_j); masked -> exp -> exactly 0.
__global__ __launch_bounds__(256) void softmax_kernel(const float* __restrict__ adj,
                                                      float* __restrict__ out) {
    __shared__ float red[8];
    const int i0 = blockIdx.x * 2;
    const int i1 = i0 + 1;
    const int t = threadIdx.x;
    const int lane = t & 31;
    const float s0 = g_s[i0];
    const float s1 = g_s[i1];

    // Warp-parallel D fold: 128 bmax = 32 float4, one per lane, 5 shfls.
    float4 mm = __ldg(&reinterpret_cast<const float4*>(g_bmax)[lane]);
    float D = fmaxf(fmaxf(mm.x, mm.y), fmaxf(mm.z, mm.w));
    #pragma unroll
    for (int o = 16; o > 0; o >>= 1)
        D = fmaxf(D, __shfl_xor_sync(0xffffffffu, D, o));
    float M0 = s0 + D; M0 = M0 >= 0.f ? M0 : NEG_SLOPE * M0;
    float M1 = s1 + D; M1 = M1 >= 0.f ? M1 : NEG_SLOPE * M1;

    const float4* ap0 = reinterpret_cast<const float4*>(adj + (size_t)i0 * N_NODES);
    const float4* ap1 = reinterpret_cast<const float4*>(adj + (size_t)i1 * N_NODES);
    const float4* dp  = reinterpret_cast<const float4*>(g_d);

    // ---- Row A: load + lrelu + exp + sum ----
    float4 eA[8];
    float lsum0 = 0.f;
    #pragma unroll
    for (int k = 0; k < 8; ++k) {
        const int c = t + k * 256;
        float4 av = __ldcs(&ap0[c]);
        float4 dv = __ldg(&dp[c]);
        float v0 = s0 + dv.x; v0 = v0 >= 0.f ? v0 : NEG_SLOPE * v0; v0 = (av.x > 0.f) ? v0 : -VERY_SMALL;
        float v1 = s0 + dv.y; v1 = v1 >= 0.f ? v1 : NEG_SLOPE * v1; v1 = (av.y > 0.f) ? v1 : -VERY_SMALL;
        float v2 = s0 + dv.z; v2 = v2 >= 0.f ? v2 : NEG_SLOPE * v2; v2 = (av.z > 0.f) ? v2 : -VERY_SMALL;
        float v3 = s0 + dv.w; v3 = v3 >= 0.f ? v3 : NEG_SLOPE * v3; v3 = (av.w > 0.f) ? v3 : -VERY_SMALL;
        eA[k].x = __expf(v0 - M0);
        eA[k].y = __expf(v1 - M0);
        eA[k].z = __expf(v2 - M0);
        eA[k].w = __expf(v3 - M0);
        lsum0 += (eA[k].x + eA[k].y) + (eA[k].z + eA[k].w);
    }

    // ---- Issue row B loads before row A's reduce (fills the bubble) ----
    float4 eB[8];
    #pragma unroll
    for (int k = 0; k < 8; ++k)
        eB[k] = __ldcs(&ap1[t + k * 256]);

    const float inv0 = 1.0f / block_reduce_sum(lsum0, red);

    float4* op0 = reinterpret_cast<float4*>(out + (size_t)i0 * N_NODES);
    #pragma unroll
    for (int k = 0; k < 8; ++k) {
        float4 o = eA[k];
        o.x *= inv0; o.y *= inv0; o.z *= inv0; o.w *= inv0;
        __stcs(&op0[t + k * 256], o);
    }

    // ---- Row B: lrelu + exp + sum (loads already in flight) ----
    float lsum1 = 0.f;
    #pragma unroll
    for (int k = 0; k < 8; ++k) {
        const int c = t + k * 256;
        float4 dv = __ldg(&dp[c]);
        float4 av = eB[k];
        float v0 = s1 + dv.x; v0 = v0 >= 0.f ? v0 : NEG_SLOPE * v0; v0 = (av.x > 0.f) ? v0 : -VERY_SMALL;
        float v1 = s1 + dv.y; v1 = v1 >= 0.f ? v1 : NEG_SLOPE * v1; v1 = (av.y > 0.f) ? v1 : -VERY_SMALL;
        float v2 = s1 + dv.z; v2 = v2 >= 0.f ? v2 : NEG_SLOPE * v2; v2 = (av.z > 0.f) ? v2 : -VERY_SMALL;
        float v3 = s1 + dv.w; v3 = v3 >= 0.f ? v3 : NEG_SLOPE * v3; v3 = (av.w > 0.f) ? v3 : -VERY_SMALL;
        eB[k].x = __expf(v0 - M1);
        eB[k].y = __expf(v1 - M1);
        eB[k].z = __expf(v2 - M1);
        eB[k].w = __expf(v3 - M1);
        lsum1 += (eB[k].x + eB[k].y) + (eB[k].z + eB[k].w);
    }
    const float inv1 = 1.0f / block_reduce_sum(lsum1, red);

    float4* op1 = reinterpret_cast<float4*>(out + (size_t)i1 * N_NODES);
    #pragma unroll
    for (int k = 0; k < 8; ++k) {
        float4 o = eB[k];
        o.x *= inv1; o.y *= inv1; o.z *= inv1; o.w *= inv1;
        __stcs(&op1[t + k * 256], o);
    }
}

extern "C" void kernel_launch(void* const* d_in, const int* in_sizes, int n_in,
                              void* d_out, int out_size) {
    const float* h   = (const float*)d_in[0];  // [8192,128]
    const float* adj = (const float*)d_in[1];  // [8192,8192]
    const float* w   = (const float*)d_in[2];  // [128,64]
    const float* a   = (const float*)d_in[3];  // [128,1]
    float* out = (float*)d_out;

    sd_kernel<<<SD_BLOCKS, 256>>>(h, w, a);
    softmax_kernel<<<N_NODES / 2, 256>>>(adj, out);
}